// round 4
// baseline (speedup 1.0000x reference)
#include <cuda_runtime.h>
#include <math.h>

#define D_MODEL 128
#define D_STATE 64
#define LSEQ    1024
#define BATCH   32

typedef unsigned long long u64t;

__device__ __forceinline__ void fma2(u64t& d, u64t a, u64t b) {
    asm("fma.rn.f32x2 %0, %1, %2, %0;" : "+l"(d) : "l"(a), "l"(b));
}
__device__ __forceinline__ u64t pack2(float lo, float hi) {
    u64t r; asm("mov.b64 %0, {%1, %2};" : "=l"(r) : "f"(lo), "f"(hi)); return r;
}
__device__ __forceinline__ void unpack2(u64t v, float& lo, float& hi) {
    asm("mov.b64 {%0, %1}, %2;" : "=f"(lo), "=f"(hi) : "l"(v));
}

// Scratch (static device globals: allocation-free per harness rules)
__device__ float g_Krev[D_MODEL * LSEQ];                 // K reversed in time
__device__ float g_act [BATCH * D_MODEL * LSEQ];         // post-GELU activations (16 MB)

// ---------------------------------------------------------------------------
// Kernel A: K[d,l] = Re( sum_n C_n * (A_bar-1)/A * B_n * exp(A*dt*l) )
// stored reversed: g_Krev[d][1023-l] = K[d][l]
// ---------------------------------------------------------------------------
__global__ void k_genK(const float* __restrict__ log_dt,
                       const float* __restrict__ log_A_real,
                       const float* __restrict__ A_imag,
                       const float* __restrict__ B_re, const float* __restrict__ B_im,
                       const float* __restrict__ C_re, const float* __restrict__ C_im)
{
    const int d = blockIdx.x;
    __shared__ float arS[64], aiS[64], grS[64], giS[64];
    const int tid = threadIdx.x;

    const double INV2PI = 0.15915494309189535;
    const double TWOPI  = 6.283185307179586;

    if (tid < 64) {
        int n = tid;
        float dtv = expf(log_dt[d]);
        float Ar  = -expf(log_A_real[d * 64 + n]);
        float Ai  = A_imag[d * 64 + n];
        float ar  = Ar * dtv;
        float ai  = Ai * dtv;
        double aid = (double)ai;
        float r0 = (float)(aid - rint(aid * INV2PI) * TWOPI);
        float s, c;
        __sincosf(r0, &s, &c);
        float e   = expf(ar);
        float Abr = e * c, Abi = e * s;
        float nr = Abr - 1.0f, ni = Abi;
        float inv = 1.0f / (Ar * Ar + Ai * Ai);
        float br = (nr * Ar + ni * Ai) * inv;
        float bi = (ni * Ar - nr * Ai) * inv;
        float Br = B_re[d * 64 + n], Bi = B_im[d * 64 + n];
        float tr = br * Br - bi * Bi;
        float ti = br * Bi + bi * Br;
        float Cr = C_re[d * 64 + n], Ci = C_im[d * 64 + n];
        grS[n] = Cr * tr - Ci * ti;
        giS[n] = Cr * ti + Ci * tr;
        arS[n] = ar;
        aiS[n] = ai;
    }
    __syncthreads();

    for (int l = tid; l < LSEQ; l += blockDim.x) {
        float lf = (float)l;
        float acc = 0.0f;
        #pragma unroll 4
        for (int n = 0; n < 64; n++) {
            float ph = aiS[n] * lf;                    // fp32 phase (matches reference rounding)
            double phd = (double)ph;
            float r = (float)(phd - rint(phd * INV2PI) * TWOPI);  // exact mod-2pi of ph
            float s, c;
            __sincosf(r, &s, &c);
            float e = __expf(arS[n] * lf);
            acc += e * (grS[n] * c - giS[n] * s);
        }
        g_Krev[d * LSEQ + (LSEQ - 1 - l)] = acc;
    }
}

// ---------------------------------------------------------------------------
// Kernel B: depthwise causal conv (reversed kernel) + skip + Cheb-GELU.
// f32x2 packed: outputs paired over l. us0 = zero-padded u row; us1 = us0
// shifted by one float (so odd-offset pairs are vector-loadable); Kd = K
// duplicated pairwise (broadcast multiplier via one LDS.64).
// One block per (b,d). 128 threads, 8 outputs each.
// ---------------------------------------------------------------------------
__global__ void __launch_bounds__(128) k_conv(const float* __restrict__ u,
                                              const float* __restrict__ Dvec)
{
    __shared__ __align__(16) float us0[2 * LSEQ];
    __shared__ __align__(16) float us1[2 * LSEQ];
    __shared__ __align__(16) float Kd[2 * LSEQ];

    const int d = blockIdx.x & (D_MODEL - 1);
    const int b = blockIdx.x >> 7;
    const int tid = threadIdx.x;

    const float* urow = u + (size_t)(b * D_MODEL + d) * LSEQ;
    const float* krow = g_Krev + d * LSEQ;
    for (int i = tid; i < 2 * LSEQ; i += 128) {
        us0[i] = (i < LSEQ) ? 0.0f : urow[i - LSEQ];
        us1[i] = (i >= LSEQ - 1 && i < 2 * LSEQ - 1) ? urow[i - (LSEQ - 1)] : 0.0f;
    }
    for (int i = tid; i < LSEQ; i += 128) {
        float kv = krow[i];
        Kd[2 * i]     = kv;
        Kd[2 * i + 1] = kv;
    }
    __syncthreads();

    const int l0 = tid * 8;
    u64t y2[4];
    #pragma unroll
    for (int j = 0; j < 4; j++) y2[j] = 0ull;

    for (int t = 0; t <= l0; t += 8) {
        const int base = LSEQ + l0 - t - 8;
        // p[m] = (us0[base+2m], us0[base+2m+1]),  m=0..7
        ulonglong2 P0 = *(const ulonglong2*)&us0[base];
        ulonglong2 P1 = *(const ulonglong2*)&us0[base + 4];
        ulonglong2 P2 = *(const ulonglong2*)&us0[base + 8];
        ulonglong2 P3 = *(const ulonglong2*)&us0[base + 12];
        // q[m] = (us0[base+2m+1], us0[base+2m+2])
        ulonglong2 Q0 = *(const ulonglong2*)&us1[base];
        ulonglong2 Q1 = *(const ulonglong2*)&us1[base + 4];
        ulonglong2 Q2 = *(const ulonglong2*)&us1[base + 8];
        ulonglong2 Q3 = *(const ulonglong2*)&us1[base + 12];
        u64t p[8] = {P0.x, P0.y, P1.x, P1.y, P2.x, P2.y, P3.x, P3.y};
        u64t q[8] = {Q0.x, Q0.y, Q1.x, Q1.y, Q2.x, Q2.y, Q3.x, Q3.y};
        u64t kp[8];
        #pragma unroll
        for (int s = 0; s < 8; s++)
            kp[s] = *(const u64t*)&Kd[2 * (t + s)];

        // even s: pair index m = 4 - s/2 + j2   (in p)
        // odd  s: pair index m = (7-s)/2 + j2   (in q)
        #pragma unroll
        for (int s = 0; s < 8; s += 2) {
            #pragma unroll
            for (int j2 = 0; j2 < 4; j2++)
                fma2(y2[j2], kp[s], p[4 - s / 2 + j2]);
        }
        #pragma unroll
        for (int s = 1; s < 8; s += 2) {
            #pragma unroll
            for (int j2 = 0; j2 < 4; j2++)
                fma2(y2[j2], kp[s], q[(7 - s) / 2 + j2]);
        }
    }

    float y[8];
    #pragma unroll
    for (int j2 = 0; j2 < 4; j2++) unpack2(y2[j2], y[2 * j2], y[2 * j2 + 1]);

    // skip + Chebyshev GELU (degree 6, domain [-5,15])
    const float Dd = Dvec[d];
    float* gout = g_act + (size_t)(b * D_MODEL + d) * LSEQ + l0;
    const float cc[5] = {1.371512430522f, -0.740775295685f, 0.134773988002f,
                         0.126019270103f, -0.239569101196f};
    #pragma unroll
    for (int j = 0; j < 8; j++) {
        float x = y[j] + us0[LSEQ + l0 + j] * Dd;
        float t = (2.0f * x - 10.0f) * 0.05f;
        float t0 = 1.0f, t1 = t;
        float res = 6.04831644882f + 8.094460228971f * t;
        #pragma unroll
        for (int i = 0; i < 5; i++) {
            float ti = 2.0f * t * t1 - t0;
            res += cc[i] * ti;
            t0 = t1; t1 = ti;
        }
        gout[j] = res;
    }
}

// ---------------------------------------------------------------------------
// Kernel C: GLU GEMM + gate + Wdec-weighted mean pool, f32x2 packed over l.
// Block = (oh half of 64 o-pairs, 256-l window, batch b). 2 blocks/SM.
//   W1T slice [128 d][132] : cols 0..63 a-half, 64..127 b-half
//   gsh       [128 d][68]  : 64-l sub-chunk
// Thread: 4 o x 4 l (2 l-pairs) x {a,b} accumulators.
// ---------------------------------------------------------------------------
#define W1PITCH 132
#define GPITCH  68

__global__ void __launch_bounds__(256) k_head(const float* __restrict__ W1,
                                              const float* __restrict__ b1,
                                              const float* __restrict__ Wdec,
                                              float* __restrict__ out)
{
    extern __shared__ float smem[];
    float* W1T = smem;                       // 128 * 132
    float* gsh = smem + 128 * W1PITCH;       // 128 * 68
    __shared__ float red[256];

    const int tid = threadIdx.x;
    const int b   = blockIdx.y;
    const int oh  = blockIdx.x & 1;          // which 64-o half
    const int lcb = blockIdx.x >> 1;         // 256-l window index (0..3)

    // Stage W1 slice transposed: W1 is [256 o][128 d]
    for (int idx = tid; idx < 64 * 128; idx += 256) {
        int c = idx >> 7, dd = idx & 127;
        W1T[dd * W1PITCH + c]      = W1[(oh * 64 + c) * 128 + dd];
        W1T[dd * W1PITCH + 64 + c] = W1[(128 + oh * 64 + c) * 128 + dd];
    }

    const int oc = (tid >> 4) * 4;           // 0..60 within half
    const int lg = tid & 15;                 // 16 l-groups * 4 l = 64 l
    float b1a[4], b1b[4], wd[4];
    #pragma unroll
    for (int i = 0; i < 4; i++) {
        int o = oh * 64 + oc + i;
        b1a[i] = b1[o];
        b1b[i] = b1[o + 128];
        wd[i]  = Wdec[o];
    }

    float partial = 0.0f;
    const float* gbase = g_act + (size_t)b * D_MODEL * LSEQ + lcb * 256;

    for (int sc = 0; sc < 4; sc++) {
        __syncthreads();                     // also orders W1T before first use
        const float* gsrc = gbase + sc * 64;
        for (int idx = tid; idx < 128 * 64; idx += 256) {
            int dd = idx >> 6, ll = idx & 63;
            gsh[dd * GPITCH + ll] = gsrc[dd * 1024 + ll];
        }
        __syncthreads();

        u64t accA[4][2], accB[4][2];
        #pragma unroll
        for (int i = 0; i < 4; i++)
            #pragma unroll
            for (int j = 0; j < 2; j++) { accA[i][j] = 0ull; accB[i][j] = 0ull; }

        #pragma unroll 2
        for (int dd = 0; dd < 128; dd++) {
            float4 wa = *(const float4*)&W1T[dd * W1PITCH + oc];
            float4 wb = *(const float4*)&W1T[dd * W1PITCH + 64 + oc];
            ulonglong2 gp = *(const ulonglong2*)&gsh[dd * GPITCH + lg * 4];
            u64t g2[2] = {gp.x, gp.y};
            u64t wpa[4] = {pack2(wa.x, wa.x), pack2(wa.y, wa.y),
                           pack2(wa.z, wa.z), pack2(wa.w, wa.w)};
            u64t wpb[4] = {pack2(wb.x, wb.x), pack2(wb.y, wb.y),
                           pack2(wb.z, wb.z), pack2(wb.w, wb.w)};
            #pragma unroll
            for (int oi = 0; oi < 4; oi++)
                #pragma unroll
                for (int lp = 0; lp < 2; lp++) {
                    fma2(accA[oi][lp], wpa[oi], g2[lp]);
                    fma2(accB[oi][lp], wpb[oi], g2[lp]);
                }
        }

        #pragma unroll
        for (int oi = 0; oi < 4; oi++)
            #pragma unroll
            for (int lp = 0; lp < 2; lp++) {
                float a0, a1, bb0, bb1;
                unpack2(accA[oi][lp], a0, a1);
                unpack2(accB[oi][lp], bb0, bb1);
                float g0 = fminf(fmaxf(0.25f * (bb0 + b1b[oi]) + 0.5f, 0.0f), 1.0f);
                float g1 = fminf(fmaxf(0.25f * (bb1 + b1b[oi]) + 0.5f, 0.0f), 1.0f);
                partial += wd[oi] * ((a0 + b1a[oi]) * g0 + (a1 + b1a[oi]) * g1);
            }
    }

    red[tid] = partial;
    __syncthreads();
    for (int s = 128; s > 0; s >>= 1) {
        if (tid < s) red[tid] += red[tid + s];
        __syncthreads();
    }
    if (tid == 0) atomicAdd(out + b, red[0] * (1.0f / 1024.0f));
}

__global__ void k_init(float* out, const float* __restrict__ bdec)
{
    int i = threadIdx.x;
    if (i < BATCH) out[i] = bdec[0];
}

// ---------------------------------------------------------------------------
extern "C" void kernel_launch(void* const* d_in, const int* in_sizes, int n_in,
                              void* d_out, int out_size)
{
    const float* u          = (const float*)d_in[0];
    const float* log_dt     = (const float*)d_in[1];
    const float* log_A_real = (const float*)d_in[2];
    const float* A_imag     = (const float*)d_in[3];
    const float* B_re       = (const float*)d_in[4];
    const float* B_im       = (const float*)d_in[5];
    const float* C_re       = (const float*)d_in[6];
    const float* C_im       = (const float*)d_in[7];
    const float* Dvec       = (const float*)d_in[8];
    const float* W1         = (const float*)d_in[9];
    const float* b1         = (const float*)d_in[10];
    const float* Wdec       = (const float*)d_in[11];
    const float* bdec       = (const float*)d_in[12];
    float* out = (float*)d_out;

    const int smemC = (128 * W1PITCH + 128 * GPITCH) * (int)sizeof(float);  // 102400 B
    cudaFuncSetAttribute(k_head, cudaFuncAttributeMaxDynamicSharedMemorySize, smemC);

    k_init<<<1, 32>>>(out, bdec);
    k_genK<<<D_MODEL, 256>>>(log_dt, log_A_real, A_imag, B_re, B_im, C_re, C_im);
    k_conv<<<BATCH * D_MODEL, 128>>>(u, Dvec);
    k_head<<<dim3(8, BATCH), 256, smemC>>>(W1, b1, Wdec, out);
}

// round 5
// speedup vs baseline: 2.1389x; 2.1389x over previous
#include <cuda_runtime.h>
#include <math.h>

#define D_MODEL 128
#define D_STATE 64
#define LSEQ    1024
#define BATCH   32

// Scratch (static device globals: allocation-free per harness rules)
__device__ float g_Krev[D_MODEL * LSEQ];                 // K reversed in time
__device__ float g_act [BATCH * D_MODEL * LSEQ];         // post-GELU activations (16 MB)

// ---------------------------------------------------------------------------
// Kernel A: K[d,l] = Re( sum_n C_n * (A_bar-1)/A * B_n * exp(A*dt*l) )
// stored reversed: g_Krev[d][1023-l] = K[d][l]
// grid (d, 4 l-chunks) x 256 threads
// ---------------------------------------------------------------------------
__global__ void k_genK(const float* __restrict__ log_dt,
                       const float* __restrict__ log_A_real,
                       const float* __restrict__ A_imag,
                       const float* __restrict__ B_re, const float* __restrict__ B_im,
                       const float* __restrict__ C_re, const float* __restrict__ C_im)
{
    const int d = blockIdx.x;
    __shared__ float arS[64], aiS[64], grS[64], giS[64];
    const int tid = threadIdx.x;

    const double INV2PI = 0.15915494309189535;
    const double TWOPI  = 6.283185307179586;

    if (tid < 64) {
        int n = tid;
        float dtv = expf(log_dt[d]);
        float Ar  = -expf(log_A_real[d * 64 + n]);
        float Ai  = A_imag[d * 64 + n];
        float ar  = Ar * dtv;
        float ai  = Ai * dtv;
        double aid = (double)ai;
        float r0 = (float)(aid - rint(aid * INV2PI) * TWOPI);
        float s, c;
        __sincosf(r0, &s, &c);
        float e   = expf(ar);
        float Abr = e * c, Abi = e * s;
        float nr = Abr - 1.0f, ni = Abi;
        float inv = 1.0f / (Ar * Ar + Ai * Ai);
        float br = (nr * Ar + ni * Ai) * inv;
        float bi = (ni * Ar - nr * Ai) * inv;
        float Br = B_re[d * 64 + n], Bi = B_im[d * 64 + n];
        float tr = br * Br - bi * Bi;
        float ti = br * Bi + bi * Br;
        float Cr = C_re[d * 64 + n], Ci = C_im[d * 64 + n];
        grS[n] = Cr * tr - Ci * ti;
        giS[n] = Cr * ti + Ci * tr;
        arS[n] = ar;
        aiS[n] = ai;
    }
    __syncthreads();

    const int l = blockIdx.y * 256 + tid;
    {
        float lf = (float)l;
        float acc = 0.0f;
        #pragma unroll 4
        for (int n = 0; n < 64; n++) {
            float ph = aiS[n] * lf;                    // fp32 phase (matches reference rounding)
            double phd = (double)ph;
            float r = (float)(phd - rint(phd * INV2PI) * TWOPI);  // exact mod-2pi of ph
            float s, c;
            __sincosf(r, &s, &c);
            float e = __expf(arS[n] * lf);
            acc += e * (grS[n] * c - giS[n] * s);
        }
        g_Krev[d * LSEQ + (LSEQ - 1 - l)] = acc;
    }
}

// ---------------------------------------------------------------------------
// Kernel B: depthwise causal conv (reversed kernel) + skip + Cheb-GELU.
//   y[l] = sum_{s} Krev[t+s] * us[LSEQ + l - t - s]   (zero-padded left half)
// FOLDED work assignment: thread i computes 4 outputs at lA=4i and 4 at
// lB=1020-4i  ->  exactly 1024 taps per thread, balanced within every warp.
// K-tap loads are warp-uniform (broadcast, ~free); both chunks share them.
// One block per (b,d). 128 threads.
// ---------------------------------------------------------------------------
__global__ void __launch_bounds__(128) k_conv(const float* __restrict__ u,
                                              const float* __restrict__ Dvec)
{
    __shared__ __align__(16) float us[2 * LSEQ];   // [0,1024) zeros, [1024,2048) u row
    __shared__ __align__(16) float Ks[LSEQ];

    const int d = blockIdx.x & (D_MODEL - 1);
    const int b = blockIdx.x >> 7;
    const int tid = threadIdx.x;

    const float* urow = u + (size_t)(b * D_MODEL + d) * LSEQ;
    const float* krow = g_Krev + d * LSEQ;
    for (int i = tid; i < LSEQ; i += 128) {
        us[i]        = 0.0f;
        us[LSEQ + i] = urow[i];
        Ks[i]        = krow[i];
    }
    __syncthreads();

    const int lA = 4 * tid;          // [0, 512)
    const int lB = 1020 - 4 * tid;   // [512, 1024)
    const int boundA = lA + 3;
    const int boundB = lB + 3;

    float yA[4] = {0.f, 0.f, 0.f, 0.f};
    float yB[4] = {0.f, 0.f, 0.f, 0.f};

    for (int t = 0; t <= boundB; t += 8) {
        float4 k0 = *(const float4*)&Ks[t];        // warp-uniform -> broadcast
        float4 k1 = *(const float4*)&Ks[t + 4];
        float kk[8] = {k0.x, k0.y, k0.z, k0.w, k1.x, k1.y, k1.z, k1.w};

        // chunk B (always active in this loop)
        {
            const int base = LSEQ + lB - t - 8;    // multiple of 4
            float4 u0 = *(const float4*)&us[base];
            float4 u1 = *(const float4*)&us[base + 4];
            float4 u2 = *(const float4*)&us[base + 8];
            float uu[12] = {u0.x, u0.y, u0.z, u0.w, u1.x, u1.y, u1.z, u1.w,
                            u2.x, u2.y, u2.z, u2.w};
            #pragma unroll
            for (int s = 0; s < 8; s++)
                #pragma unroll
                for (int j = 0; j < 4; j++)
                    yB[j] = fmaf(kk[s], uu[8 + j - s], yB[j]);
        }

        // chunk A (zero padding makes partial taps harmless)
        if (t <= boundA) {
            const int base = LSEQ + lA - t - 8;    // multiple of 4
            float4 u0 = *(const float4*)&us[base];
            float4 u1 = *(const float4*)&us[base + 4];
            float4 u2 = *(const float4*)&us[base + 8];
            float uu[12] = {u0.x, u0.y, u0.z, u0.w, u1.x, u1.y, u1.z, u1.w,
                            u2.x, u2.y, u2.z, u2.w};
            #pragma unroll
            for (int s = 0; s < 8; s++)
                #pragma unroll
                for (int j = 0; j < 4; j++)
                    yA[j] = fmaf(kk[s], uu[8 + j - s], yA[j]);
        }
    }

    // skip + Chebyshev GELU (degree 6, domain [-5,15])
    const float Dd = Dvec[d];
    float* gbase = g_act + (size_t)(b * D_MODEL + d) * LSEQ;
    const float cc[5] = {1.371512430522f, -0.740775295685f, 0.134773988002f,
                         0.126019270103f, -0.239569101196f};
    #pragma unroll
    for (int j = 0; j < 8; j++) {
        const int l = (j < 4) ? (lA + j) : (lB + j - 4);
        float y = (j < 4) ? yA[j] : yB[j - 4];
        float x = y + us[LSEQ + l] * Dd;
        float t = (2.0f * x - 10.0f) * 0.05f;
        float t0 = 1.0f, t1 = t;
        float res = 6.04831644882f + 8.094460228971f * t;
        #pragma unroll
        for (int i = 0; i < 5; i++) {
            float ti = 2.0f * t * t1 - t0;
            res += cc[i] * ti;
            t0 = t1; t1 = ti;
        }
        gbase[l] = res;
    }
}

// ---------------------------------------------------------------------------
// Kernel C: GLU GEMM + gate + Wdec-weighted mean pool (plain fp32).
// o split across 2 blocks -> smem 102.4KB -> 2 blocks/SM (16 warps).
//   W1T slice [128 d][132] : cols 0..63 a-half, 64..127 b-half
//   gsh       [128 d][68]  : 64-l sub-chunk
// Thread: 4 o x 4 l. Block = (oh, 256-l window) x batch. grid 8 x 32.
// ---------------------------------------------------------------------------
#define W1PITCH 132
#define GPITCH  68

__global__ void __launch_bounds__(256) k_head(const float* __restrict__ W1,
                                              const float* __restrict__ b1,
                                              const float* __restrict__ Wdec,
                                              float* __restrict__ out)
{
    extern __shared__ float smem[];
    float* W1T = smem;                       // 128 * 132
    float* gsh = smem + 128 * W1PITCH;       // 128 * 68
    __shared__ float red[256];

    const int tid = threadIdx.x;
    const int b   = blockIdx.y;
    const int oh  = blockIdx.x & 1;          // which 64-o half
    const int lcb = blockIdx.x >> 1;         // 256-l window index (0..3)

    // Stage W1 slice transposed: W1 is [256 o][128 d]; reads coalesced over dd.
    for (int idx = tid; idx < 64 * 128; idx += 256) {
        int c = idx >> 7, dd = idx & 127;
        W1T[dd * W1PITCH + c]      = W1[(oh * 64 + c) * 128 + dd];
        W1T[dd * W1PITCH + 64 + c] = W1[(128 + oh * 64 + c) * 128 + dd];
    }

    const int oc = (tid >> 4) * 4;           // 0..60 within half
    const int lg = tid & 15;                 // 16 l-groups * 4 l = 64 l
    float b1a[4], b1b[4], wd[4];
    #pragma unroll
    for (int i = 0; i < 4; i++) {
        int o = oh * 64 + oc + i;
        b1a[i] = b1[o];
        b1b[i] = b1[o + 128];
        wd[i]  = Wdec[o];
    }

    float partial = 0.0f;
    const float* gbase = g_act + (size_t)b * D_MODEL * LSEQ + lcb * 256;

    for (int sc = 0; sc < 4; sc++) {
        __syncthreads();                     // also orders W1T writes before first use
        const float* gsrc = gbase + sc * 64;
        for (int idx = tid; idx < 128 * 64; idx += 256) {
            int dd = idx >> 6, ll = idx & 63;
            gsh[dd * GPITCH + ll] = gsrc[dd * 1024 + ll];
        }
        __syncthreads();

        float accA[4][4], accB[4][4];
        #pragma unroll
        for (int i = 0; i < 4; i++)
            #pragma unroll
            for (int j = 0; j < 4; j++) { accA[i][j] = 0.0f; accB[i][j] = 0.0f; }

        #pragma unroll 2
        for (int dd = 0; dd < 128; dd++) {
            float4 wa = *(const float4*)&W1T[dd * W1PITCH + oc];
            float4 wb = *(const float4*)&W1T[dd * W1PITCH + 64 + oc];
            float4 g4 = *(const float4*)&gsh[dd * GPITCH + lg * 4];
            float gg[4]  = {g4.x, g4.y, g4.z, g4.w};
            float wav[4] = {wa.x, wa.y, wa.z, wa.w};
            float wbv[4] = {wb.x, wb.y, wb.z, wb.w};
            #pragma unroll
            for (int oi = 0; oi < 4; oi++)
                #pragma unroll
                for (int li = 0; li < 4; li++) {
                    accA[oi][li] = fmaf(wav[oi], gg[li], accA[oi][li]);
                    accB[oi][li] = fmaf(wbv[oi], gg[li], accB[oi][li]);
                }
        }

        #pragma unroll
        for (int oi = 0; oi < 4; oi++)
            #pragma unroll
            for (int li = 0; li < 4; li++) {
                float a    = accA[oi][li] + b1a[oi];
                float bb   = accB[oi][li] + b1b[oi];
                float gate = fminf(fmaxf(0.25f * bb + 0.5f, 0.0f), 1.0f);
                partial += wd[oi] * (a * gate);
            }
    }

    red[tid] = partial;
    __syncthreads();
    for (int s = 128; s > 0; s >>= 1) {
        if (tid < s) red[tid] += red[tid + s];
        __syncthreads();
    }
    if (tid == 0) atomicAdd(out + b, red[0] * (1.0f / 1024.0f));
}

__global__ void k_init(float* out, const float* __restrict__ bdec)
{
    int i = threadIdx.x;
    if (i < BATCH) out[i] = bdec[0];
}

// ---------------------------------------------------------------------------
extern "C" void kernel_launch(void* const* d_in, const int* in_sizes, int n_in,
                              void* d_out, int out_size)
{
    const float* u          = (const float*)d_in[0];
    const float* log_dt     = (const float*)d_in[1];
    const float* log_A_real = (const float*)d_in[2];
    const float* A_imag     = (const float*)d_in[3];
    const float* B_re       = (const float*)d_in[4];
    const float* B_im       = (const float*)d_in[5];
    const float* C_re       = (const float*)d_in[6];
    const float* C_im       = (const float*)d_in[7];
    const float* Dvec       = (const float*)d_in[8];
    const float* W1         = (const float*)d_in[9];
    const float* b1         = (const float*)d_in[10];
    const float* Wdec       = (const float*)d_in[11];
    const float* bdec       = (const float*)d_in[12];
    float* out = (float*)d_out;

    const int smemC = (128 * W1PITCH + 128 * GPITCH) * (int)sizeof(float);  // 102400 B
    cudaFuncSetAttribute(k_head, cudaFuncAttributeMaxDynamicSharedMemorySize, smemC);

    k_init<<<1, 32>>>(out, bdec);
    k_genK<<<dim3(D_MODEL, 4), 256>>>(log_dt, log_A_real, A_imag, B_re, B_im, C_re, C_im);
    k_conv<<<BATCH * D_MODEL, 128>>>(u, Dvec);
    k_head<<<dim3(8, BATCH), 256, smemC>>>(W1, b1, Wdec, out);
}

// round 9
// speedup vs baseline: 2.9711x; 1.3891x over previous
#include <cuda_runtime.h>
#include <cuda_bf16.h>
#include <math.h>
#include <stdint.h>

#define D_MODEL 128
#define D_STATE 64
#define LSEQ    1024
#define BATCH   32

// Scratch (static device globals: allocation-free per harness rules)
__device__ float g_K  [D_MODEL * LSEQ];                  // REVERSED kernel Krev[d][s] = K[d][1023-s]
__device__ float g_act[BATCH * D_MODEL * LSEQ];          // post-GELU activations

// ---------------------------------------------------------------------------
// helpers
// ---------------------------------------------------------------------------
__device__ __forceinline__ uint16_t bfbits(float x) {
    __nv_bfloat16 h = __float2bfloat16(x);
    return *(uint16_t*)&h;
}
__device__ __forceinline__ float bf2f(uint16_t b) {
    __nv_bfloat16 h = *(__nv_bfloat16*)&b;
    return __bfloat162float(h);
}
// mma.sync m16n8k16 row.col f32.bf16.bf16.f32 (sm_80+, no 'a' feature needed)
__device__ __forceinline__ void mma16816(float* c, const uint32_t* a, const uint32_t* b) {
    asm volatile(
        "mma.sync.aligned.m16n8k16.row.col.f32.bf16.bf16.f32 "
        "{%0,%1,%2,%3}, {%4,%5,%6,%7}, {%8,%9}, {%0,%1,%2,%3};"
        : "+f"(c[0]), "+f"(c[1]), "+f"(c[2]), "+f"(c[3])
        : "r"(a[0]), "r"(a[1]), "r"(a[2]), "r"(a[3]), "r"(b[0]), "r"(b[1]));
}

// ---------------------------------------------------------------------------
// Kernel A: K[d,m] = Re( sum_n C_n * (A_bar-1)/A * B_n * exp(A*dt*m) )
// STORED REVERSED (the conv with left-pad L-1 applies the reversed kernel):
//   g_K[d][1023-m] = K[d][m]
// ---------------------------------------------------------------------------
__global__ void k_genK(const float* __restrict__ log_dt,
                       const float* __restrict__ log_A_real,
                       const float* __restrict__ A_imag,
                       const float* __restrict__ B_re, const float* __restrict__ B_im,
                       const float* __restrict__ C_re, const float* __restrict__ C_im)
{
    const int d = blockIdx.x;
    __shared__ float arS[64], aiS[64], grS[64], giS[64];
    const int tid = threadIdx.x;
    const double INV2PI = 0.15915494309189535;
    const double TWOPI  = 6.283185307179586;

    if (tid < 64) {
        int n = tid;
        float dtv = expf(log_dt[d]);
        float Ar  = -expf(log_A_real[d * 64 + n]);
        float Ai  = A_imag[d * 64 + n];
        float ar  = Ar * dtv;
        float ai  = Ai * dtv;
        double aid = (double)ai;
        float r0 = (float)(aid - rint(aid * INV2PI) * TWOPI);
        float s, c;
        __sincosf(r0, &s, &c);
        float e   = expf(ar);
        float Abr = e * c, Abi = e * s;
        float nr = Abr - 1.0f, ni = Abi;
        float inv = 1.0f / (Ar * Ar + Ai * Ai);
        float br = (nr * Ar + ni * Ai) * inv;
        float bi = (ni * Ar - nr * Ai) * inv;
        float Br = B_re[d * 64 + n], Bi = B_im[d * 64 + n];
        float tr = br * Br - bi * Bi;
        float ti = br * Bi + bi * Br;
        float Cr = C_re[d * 64 + n], Ci = C_im[d * 64 + n];
        grS[n] = Cr * tr - Ci * ti;
        giS[n] = Cr * ti + Ci * tr;
        arS[n] = ar;
        aiS[n] = ai;
    }
    __syncthreads();

    const int l = blockIdx.y * 256 + tid;
    float lf = (float)l;
    float acc = 0.0f;
    #pragma unroll 4
    for (int n = 0; n < 64; n++) {
        float ph = aiS[n] * lf;
        double phd = (double)ph;
        float r = (float)(phd - rint(phd * INV2PI) * TWOPI);
        float s, c;
        __sincosf(r, &s, &c);
        float e = __expf(arS[n] * lf);
        acc += e * (grS[n] * c - giS[n] * s);
    }
    g_K[d * LSEQ + (LSEQ - 1 - l)] = acc;     // reversed store
}

// ---------------------------------------------------------------------------
// Kernel B: per-d Toeplitz conv via mma.sync bf16 hi/lo split (3 terms).
//   y[l,b] = sum_k Krev[l-k] u[b,k]   (Krev = g_K row, already reversed)
//   A[m,k]=Krev[l-k]: with p = 128 + l - k, A fragments come from 1D pair
//   arrays AH/AL. Fragment map: a0=AHl[p], a1(row+8)=AHl[p+8],
//   a2(k+8)=AHl[p-8], a3=a0.
// One CTA per d (grid 128), 256 threads = 8 warps; warp w owns m16-row w of
// each 128-row output chunk j, all 4 n8 tiles; accumulate k-chunks 0..8(j+1)-1.
// Epilogue per j: stage to smem -> coalesced skip + Cheb-GELU -> g_act.
// ---------------------------------------------------------------------------
#define PKB      2064                     // ub row pitch bytes (1032 bf16)
#define OFF_AH   0                        // 1160 u32 = 4640 B
#define OFF_AL   4640
#define OFF_STG  9280                     // 32*136 floats = 17408 B (also K scratch)
#define OFF_UBH  26688                    // 32 * 2064 = 66048 B
#define OFF_UBL  92736
#define SMEM_CONV 158784

__global__ void __launch_bounds__(256, 1) k_conv(const float* __restrict__ u,
                                                 const float* __restrict__ Dvec)
{
    extern __shared__ __align__(16) char smem[];
    uint32_t* AH  = (uint32_t*)(smem + OFF_AH);
    uint32_t* AL  = (uint32_t*)(smem + OFF_AL);
    float*    stg = (float*)(smem + OFF_STG);

    const int d    = blockIdx.x;
    const int tid  = threadIdx.x;
    const int w    = tid >> 5;
    const int lane = tid & 31;

    // ---- Krev fp32 into scratch ----
    for (int i = tid; i < 1024; i += 256) stg[i] = g_K[d * LSEQ + i];
    __syncthreads();

    // ---- build A pair arrays: logical index il in [-8, 1151], raw = il + 8 ----
    // AH[raw] = pack(bf16hi(Krev[il-128]), bf16hi(Krev[il-129])), zeros outside
    for (int i = tid; i < 1160; i += 256) {
        int il = i - 8;
        float k0 = (il  >= 128 && il  <= 1151) ? stg[il  - 128] : 0.0f;
        float k1 = (il-1 >= 128 && il-1 <= 1151) ? stg[il - 129] : 0.0f;
        uint16_t h0 = bfbits(k0), h1 = bfbits(k1);
        uint16_t l0 = bfbits(k0 - bf2f(h0)), l1 = bfbits(k1 - bf2f(h1));
        AH[i] = (uint32_t)h0 | ((uint32_t)h1 << 16);
        AL[i] = (uint32_t)l0 | ((uint32_t)l1 << 16);
    }

    // ---- build u strip bf16 hi/lo: ub[n][k], pitch 1032 bf16 ----
    for (int idx = tid; idx < 8192; idx += 256) {
        int n = idx >> 8, kq = idx & 255;
        float4 v = *(const float4*)(u + ((size_t)(n * D_MODEL + d)) * LSEQ + kq * 4);
        float vv[4] = {v.x, v.y, v.z, v.w};
        uint16_t hb[4], lb[4];
        #pragma unroll
        for (int t = 0; t < 4; t++) {
            hb[t] = bfbits(vv[t]);
            lb[t] = bfbits(vv[t] - bf2f(hb[t]));
        }
        uint2 hv = { (uint32_t)hb[0] | ((uint32_t)hb[1] << 16),
                     (uint32_t)hb[2] | ((uint32_t)hb[3] << 16) };
        uint2 lv = { (uint32_t)lb[0] | ((uint32_t)lb[1] << 16),
                     (uint32_t)lb[2] | ((uint32_t)lb[3] << 16) };
        *(uint2*)(smem + OFF_UBH + n * PKB + kq * 8) = hv;
        *(uint2*)(smem + OFF_UBL + n * PKB + kq * 8) = lv;
    }
    __syncthreads();   // also: all stg (K scratch) reads done before staging reuse

    const uint32_t* AHl = AH + 8;
    const uint32_t* ALl = AL + 8;
    const int row  = lane >> 2;          // 0..7
    const int kc   = (lane & 3) * 2;     // 0,2,4,6
    const float Dd = Dvec[d];
    const float cc5[5] = {1.371512430522f, -0.740775295685f, 0.134773988002f,
                          0.126019270103f, -0.239569101196f};

    for (int j = 0; j < 8; j++) {
        float acc[4][4];
        #pragma unroll
        for (int a = 0; a < 4; a++)
            #pragma unroll
            for (int b = 0; b < 4; b++) acc[a][b] = 0.0f;

        const int nk = 8 * (j + 1);
        const int Pw = 128 + j * 128 + w * 16 + row - kc;

        for (int kk = 0; kk < nk; kk++) {
            const int k0 = kk * 16;
            const int p  = Pw - k0;
            uint32_t ah[4], al[4];
            // a0 = (r, c); a1 = (r+8, c) -> p+8; a2 = (r, c+8) -> p-8; a3 = a0
            ah[0] = AHl[p]; ah[1] = AHl[p + 8]; ah[2] = AHl[p - 8]; ah[3] = ah[0];
            al[0] = ALl[p]; al[1] = ALl[p + 8]; al[2] = ALl[p - 8]; al[3] = al[0];
            const int bofs = (k0 + kc) * 2;
            #pragma unroll
            for (int nt = 0; nt < 4; nt++) {
                const char* pb = smem + (nt * 8 + row) * PKB + bofs;   // row == lane>>2 == B col
                uint32_t bh[2] = { *(const uint32_t*)(pb + OFF_UBH),
                                   *(const uint32_t*)(pb + OFF_UBH + 16) };
                uint32_t bl[2] = { *(const uint32_t*)(pb + OFF_UBL),
                                   *(const uint32_t*)(pb + OFF_UBL + 16) };
                mma16816(acc[nt], ah, bh);
                mma16816(acc[nt], ah, bl);
                mma16816(acc[nt], al, bh);
            }
        }

        // ---- stage this 128(l) x 32(b) chunk: stg[b][l], pitch 136 ----
        #pragma unroll
        for (int nt = 0; nt < 4; nt++) {
            int bcol = nt * 8 + kc;
            int lml  = w * 16 + row;
            stg[bcol * 136 + lml]           = acc[nt][0];
            stg[(bcol + 1) * 136 + lml]     = acc[nt][1];
            stg[bcol * 136 + lml + 8]       = acc[nt][2];
            stg[(bcol + 1) * 136 + lml + 8] = acc[nt][3];
        }
        __syncthreads();

        // ---- coalesced epilogue: skip + Cheb-GELU -> g_act ----
        {
            const int bq  = tid >> 3;            // 0..31
            const int l4  = (tid & 7) * 4;       // 0..28
            #pragma unroll
            for (int i = 0; i < 4; i++) {
                const int ll = l4 + i * 32;
                const int l  = j * 128 + ll;
                float4 y4 = *(const float4*)&stg[bq * 136 + ll];
                const size_t gofs = ((size_t)(bq * D_MODEL + d)) * LSEQ + l;
                float4 u4 = *(const float4*)(u + gofs);
                float yy[4] = {y4.x, y4.y, y4.z, y4.w};
                float uu[4] = {u4.x, u4.y, u4.z, u4.w};
                float rr[4];
                #pragma unroll
                for (int t = 0; t < 4; t++) {
                    float x  = yy[t] + uu[t] * Dd;
                    float tc = (2.0f * x - 10.0f) * 0.05f;
                    float t0 = 1.0f, t1 = tc;
                    float res = 6.04831644882f + 8.094460228971f * tc;
                    #pragma unroll
                    for (int q = 0; q < 5; q++) {
                        float ti = 2.0f * tc * t1 - t0;
                        res += cc5[q] * ti;
                        t0 = t1; t1 = ti;
                    }
                    rr[t] = res;
                }
                float4 r4 = {rr[0], rr[1], rr[2], rr[3]};
                *(float4*)(g_act + gofs) = r4;
            }
        }
        __syncthreads();
    }
}

// ---------------------------------------------------------------------------
// Kernel C: GLU GEMM + gate + Wdec-weighted mean pool (scalar fp32, as R5).
// ---------------------------------------------------------------------------
#define W1PITCH 132
#define GPITCH  68

__global__ void __launch_bounds__(256) k_head(const float* __restrict__ W1,
                                              const float* __restrict__ b1,
                                              const float* __restrict__ Wdec,
                                              float* __restrict__ out)
{
    extern __shared__ float smf[];
    float* W1T = smf;
    float* gsh = smf + 128 * W1PITCH;
    __shared__ float red[256];

    const int tid = threadIdx.x;
    const int b   = blockIdx.y;
    const int oh  = blockIdx.x & 1;
    const int lcb = blockIdx.x >> 1;

    for (int idx = tid; idx < 64 * 128; idx += 256) {
        int c = idx >> 7, dd = idx & 127;
        W1T[dd * W1PITCH + c]      = W1[(oh * 64 + c) * 128 + dd];
        W1T[dd * W1PITCH + 64 + c] = W1[(128 + oh * 64 + c) * 128 + dd];
    }

    const int oc = (tid >> 4) * 4;
    const int lg = tid & 15;
    float b1a[4], b1b[4], wd[4];
    #pragma unroll
    for (int i = 0; i < 4; i++) {
        int o = oh * 64 + oc + i;
        b1a[i] = b1[o];
        b1b[i] = b1[o + 128];
        wd[i]  = Wdec[o];
    }

    float partial = 0.0f;
    const float* gbase = g_act + (size_t)b * D_MODEL * LSEQ + lcb * 256;

    for (int sc = 0; sc < 4; sc++) {
        __syncthreads();
        const float* gsrc = gbase + sc * 64;
        for (int idx = tid; idx < 128 * 64; idx += 256) {
            int dd = idx >> 6, ll = idx & 63;
            gsh[dd * GPITCH + ll] = gsrc[dd * 1024 + ll];
        }
        __syncthreads();

        float accA[4][4], accB[4][4];
        #pragma unroll
        for (int i = 0; i < 4; i++)
            #pragma unroll
            for (int j = 0; j < 4; j++) { accA[i][j] = 0.0f; accB[i][j] = 0.0f; }

        #pragma unroll 2
        for (int dd = 0; dd < 128; dd++) {
            float4 wa = *(const float4*)&W1T[dd * W1PITCH + oc];
            float4 wb = *(const float4*)&W1T[dd * W1PITCH + 64 + oc];
            float4 g4 = *(const float4*)&gsh[dd * GPITCH + lg * 4];
            float gg[4]  = {g4.x, g4.y, g4.z, g4.w};
            float wav[4] = {wa.x, wa.y, wa.z, wa.w};
            float wbv[4] = {wb.x, wb.y, wb.z, wb.w};
            #pragma unroll
            for (int oi = 0; oi < 4; oi++)
                #pragma unroll
                for (int li = 0; li < 4; li++) {
                    accA[oi][li] = fmaf(wav[oi], gg[li], accA[oi][li]);
                    accB[oi][li] = fmaf(wbv[oi], gg[li], accB[oi][li]);
                }
        }

        #pragma unroll
        for (int oi = 0; oi < 4; oi++)
            #pragma unroll
            for (int li = 0; li < 4; li++) {
                float a    = accA[oi][li] + b1a[oi];
                float bb   = accB[oi][li] + b1b[oi];
                float gate = fminf(fmaxf(0.25f * bb + 0.5f, 0.0f), 1.0f);
                partial += wd[oi] * (a * gate);
            }
    }

    red[tid] = partial;
    __syncthreads();
    for (int s = 128; s > 0; s >>= 1) {
        if (tid < s) red[tid] += red[tid + s];
        __syncthreads();
    }
    if (tid == 0) atomicAdd(out + b, red[0] * (1.0f / 1024.0f));
}

__global__ void k_init(float* out, const float* __restrict__ bdec)
{
    int i = threadIdx.x;
    if (i < BATCH) out[i] = bdec[0];
}

// ---------------------------------------------------------------------------
extern "C" void kernel_launch(void* const* d_in, const int* in_sizes, int n_in,
                              void* d_out, int out_size)
{
    const float* u          = (const float*)d_in[0];
    const float* log_dt     = (const float*)d_in[1];
    const float* log_A_real = (const float*)d_in[2];
    const float* A_imag     = (const float*)d_in[3];
    const float* B_re       = (const float*)d_in[4];
    const float* B_im       = (const float*)d_in[5];
    const float* C_re       = (const float*)d_in[6];
    const float* C_im       = (const float*)d_in[7];
    const float* Dvec       = (const float*)d_in[8];
    const float* W1         = (const float*)d_in[9];
    const float* b1         = (const float*)d_in[10];
    const float* Wdec       = (const float*)d_in[11];
    const float* bdec       = (const float*)d_in[12];
    float* out = (float*)d_out;

    cudaFuncSetAttribute(k_conv, cudaFuncAttributeMaxDynamicSharedMemorySize, SMEM_CONV);
    const int smemC = (128 * W1PITCH + 128 * GPITCH) * (int)sizeof(float);  // 102400 B
    cudaFuncSetAttribute(k_head, cudaFuncAttributeMaxDynamicSharedMemorySize, smemC);

    k_init<<<1, 32>>>(out, bdec);
    k_genK<<<dim3(D_MODEL, 4), 256>>>(log_dt, log_A_real, A_imag, B_re, B_im, C_re, C_im);
    k_conv<<<D_MODEL, 256, SMEM_CONV>>>(u, Dvec);
    k_head<<<dim3(8, BATCH), 256, smemC>>>(W1, b1, Wdec, out);
}

// round 11
// speedup vs baseline: 3.2006x; 1.0772x over previous
#include <cuda_runtime.h>
#include <cuda_bf16.h>
#include <math.h>
#include <stdint.h>

#define D_MODEL 128
#define D_STATE 64
#define LSEQ    1024
#define BATCH   32

// Scratch (static device globals: allocation-free per harness rules)
__device__ float g_K  [D_MODEL * LSEQ];                  // REVERSED kernel Krev[d][s] = K[d][1023-s]
__device__ float g_act[BATCH * D_MODEL * LSEQ];          // post-GELU activations
__device__ __nv_bfloat16 g_W1h[256 * 128];               // W1 bf16 hi
__device__ __nv_bfloat16 g_W1l[256 * 128];               // W1 bf16 lo

// ---------------------------------------------------------------------------
// helpers
// ---------------------------------------------------------------------------
__device__ __forceinline__ uint16_t bfbits(float x) {
    __nv_bfloat16 h = __float2bfloat16(x);
    return *(uint16_t*)&h;
}
__device__ __forceinline__ float bf2f(uint16_t b) {
    __nv_bfloat16 h = *(__nv_bfloat16*)&b;
    return __bfloat162float(h);
}
// mma.sync m16n8k16 row.col f32.bf16.bf16.f32 (sm_80+, no 'a' feature needed)
__device__ __forceinline__ void mma16816(float* c, const uint32_t* a, const uint32_t* b) {
    asm volatile(
        "mma.sync.aligned.m16n8k16.row.col.f32.bf16.bf16.f32 "
        "{%0,%1,%2,%3}, {%4,%5,%6,%7}, {%8,%9}, {%0,%1,%2,%3};"
        : "+f"(c[0]), "+f"(c[1]), "+f"(c[2]), "+f"(c[3])
        : "r"(a[0]), "r"(a[1]), "r"(a[2]), "r"(a[3]), "r"(b[0]), "r"(b[1]));
}

// ---------------------------------------------------------------------------
// Kernel A: K[d,m], stored REVERSED: g_K[d][1023-m] = K[d][m]
// ---------------------------------------------------------------------------
__global__ void k_genK(const float* __restrict__ log_dt,
                       const float* __restrict__ log_A_real,
                       const float* __restrict__ A_imag,
                       const float* __restrict__ B_re, const float* __restrict__ B_im,
                       const float* __restrict__ C_re, const float* __restrict__ C_im)
{
    const int d = blockIdx.x;
    __shared__ float arS[64], aiS[64], grS[64], giS[64];
    const int tid = threadIdx.x;
    const double INV2PI = 0.15915494309189535;
    const double TWOPI  = 6.283185307179586;

    if (tid < 64) {
        int n = tid;
        float dtv = expf(log_dt[d]);
        float Ar  = -expf(log_A_real[d * 64 + n]);
        float Ai  = A_imag[d * 64 + n];
        float ar  = Ar * dtv;
        float ai  = Ai * dtv;
        double aid = (double)ai;
        float r0 = (float)(aid - rint(aid * INV2PI) * TWOPI);
        float s, c;
        __sincosf(r0, &s, &c);
        float e   = expf(ar);
        float Abr = e * c, Abi = e * s;
        float nr = Abr - 1.0f, ni = Abi;
        float inv = 1.0f / (Ar * Ar + Ai * Ai);
        float br = (nr * Ar + ni * Ai) * inv;
        float bi = (ni * Ar - nr * Ai) * inv;
        float Br = B_re[d * 64 + n], Bi = B_im[d * 64 + n];
        float tr = br * Br - bi * Bi;
        float ti = br * Bi + bi * Br;
        float Cr = C_re[d * 64 + n], Ci = C_im[d * 64 + n];
        grS[n] = Cr * tr - Ci * ti;
        giS[n] = Cr * ti + Ci * tr;
        arS[n] = ar;
        aiS[n] = ai;
    }
    __syncthreads();

    const int l = blockIdx.y * 256 + tid;
    float lf = (float)l;
    float acc = 0.0f;
    #pragma unroll 4
    for (int n = 0; n < 64; n++) {
        float ph = aiS[n] * lf;
        double phd = (double)ph;
        float r = (float)(phd - rint(phd * INV2PI) * TWOPI);
        float s, c;
        __sincosf(r, &s, &c);
        float e = __expf(arS[n] * lf);
        acc += e * (grS[n] * c - giS[n] * s);
    }
    g_K[d * LSEQ + (LSEQ - 1 - l)] = acc;     // reversed store
}

// ---------------------------------------------------------------------------
// W1 hi/lo bf16 pre-split (tiny): g_W1h/g_W1l [o][d]
// ---------------------------------------------------------------------------
__global__ void k_prepW(const float* __restrict__ W1)
{
    int idx = blockIdx.x * 256 + threadIdx.x;   // 0..32767
    float v = W1[idx];
    __nv_bfloat16 h = __float2bfloat16(v);
    g_W1h[idx] = h;
    g_W1l[idx] = __float2bfloat16(v - __bfloat162float(h));
}

// ---------------------------------------------------------------------------
// Kernel B: per-d Toeplitz conv via mma.sync bf16 hi/lo split (unchanged R9).
// ---------------------------------------------------------------------------
#define PKB      2064                     // ub row pitch bytes (1032 bf16)
#define OFF_AH   0                        // 1160 u32 = 4640 B
#define OFF_AL   4640
#define OFF_STG  9280                     // 32*136 floats = 17408 B (also K scratch)
#define OFF_UBH  26688                    // 32 * 2064 = 66048 B
#define OFF_UBL  92736
#define SMEM_CONV 158784

__global__ void __launch_bounds__(256, 1) k_conv(const float* __restrict__ u,
                                                 const float* __restrict__ Dvec)
{
    extern __shared__ __align__(16) char smem[];
    uint32_t* AH  = (uint32_t*)(smem + OFF_AH);
    uint32_t* AL  = (uint32_t*)(smem + OFF_AL);
    float*    stg = (float*)(smem + OFF_STG);

    const int d    = blockIdx.x;
    const int tid  = threadIdx.x;
    const int w    = tid >> 5;
    const int lane = tid & 31;

    for (int i = tid; i < 1024; i += 256) stg[i] = g_K[d * LSEQ + i];
    __syncthreads();

    for (int i = tid; i < 1160; i += 256) {
        int il = i - 8;
        float k0 = (il  >= 128 && il  <= 1151) ? stg[il  - 128] : 0.0f;
        float k1 = (il-1 >= 128 && il-1 <= 1151) ? stg[il - 129] : 0.0f;
        uint16_t h0 = bfbits(k0), h1 = bfbits(k1);
        uint16_t l0 = bfbits(k0 - bf2f(h0)), l1 = bfbits(k1 - bf2f(h1));
        AH[i] = (uint32_t)h0 | ((uint32_t)h1 << 16);
        AL[i] = (uint32_t)l0 | ((uint32_t)l1 << 16);
    }

    for (int idx = tid; idx < 8192; idx += 256) {
        int n = idx >> 8, kq = idx & 255;
        float4 v = *(const float4*)(u + ((size_t)(n * D_MODEL + d)) * LSEQ + kq * 4);
        float vv[4] = {v.x, v.y, v.z, v.w};
        uint16_t hb[4], lb[4];
        #pragma unroll
        for (int t = 0; t < 4; t++) {
            hb[t] = bfbits(vv[t]);
            lb[t] = bfbits(vv[t] - bf2f(hb[t]));
        }
        uint2 hv = { (uint32_t)hb[0] | ((uint32_t)hb[1] << 16),
                     (uint32_t)hb[2] | ((uint32_t)hb[3] << 16) };
        uint2 lv = { (uint32_t)lb[0] | ((uint32_t)lb[1] << 16),
                     (uint32_t)lb[2] | ((uint32_t)lb[3] << 16) };
        *(uint2*)(smem + OFF_UBH + n * PKB + kq * 8) = hv;
        *(uint2*)(smem + OFF_UBL + n * PKB + kq * 8) = lv;
    }
    __syncthreads();

    const uint32_t* AHl = AH + 8;
    const uint32_t* ALl = AL + 8;
    const int row  = lane >> 2;
    const int kc   = (lane & 3) * 2;
    const float Dd = Dvec[d];
    const float cc5[5] = {1.371512430522f, -0.740775295685f, 0.134773988002f,
                          0.126019270103f, -0.239569101196f};

    for (int j = 0; j < 8; j++) {
        float acc[4][4];
        #pragma unroll
        for (int a = 0; a < 4; a++)
            #pragma unroll
            for (int b = 0; b < 4; b++) acc[a][b] = 0.0f;

        const int nk = 8 * (j + 1);
        const int Pw = 128 + j * 128 + w * 16 + row - kc;

        for (int kk = 0; kk < nk; kk++) {
            const int k0 = kk * 16;
            const int p  = Pw - k0;
            uint32_t ah[4], al[4];
            ah[0] = AHl[p]; ah[1] = AHl[p + 8]; ah[2] = AHl[p - 8]; ah[3] = ah[0];
            al[0] = ALl[p]; al[1] = ALl[p + 8]; al[2] = ALl[p - 8]; al[3] = al[0];
            const int bofs = (k0 + kc) * 2;
            #pragma unroll
            for (int nt = 0; nt < 4; nt++) {
                const char* pb = smem + (nt * 8 + row) * PKB + bofs;
                uint32_t bh[2] = { *(const uint32_t*)(pb + OFF_UBH),
                                   *(const uint32_t*)(pb + OFF_UBH + 16) };
                uint32_t bl[2] = { *(const uint32_t*)(pb + OFF_UBL),
                                   *(const uint32_t*)(pb + OFF_UBL + 16) };
                mma16816(acc[nt], ah, bh);
                mma16816(acc[nt], ah, bl);
                mma16816(acc[nt], al, bh);
            }
        }

        #pragma unroll
        for (int nt = 0; nt < 4; nt++) {
            int bcol = nt * 8 + kc;
            int lml  = w * 16 + row;
            stg[bcol * 136 + lml]           = acc[nt][0];
            stg[(bcol + 1) * 136 + lml]     = acc[nt][1];
            stg[bcol * 136 + lml + 8]       = acc[nt][2];
            stg[(bcol + 1) * 136 + lml + 8] = acc[nt][3];
        }
        __syncthreads();

        {
            const int bq  = tid >> 3;
            const int l4  = (tid & 7) * 4;
            #pragma unroll
            for (int i = 0; i < 4; i++) {
                const int ll = l4 + i * 32;
                const int l  = j * 128 + ll;
                float4 y4 = *(const float4*)&stg[bq * 136 + ll];
                const size_t gofs = ((size_t)(bq * D_MODEL + d)) * LSEQ + l;
                float4 u4 = *(const float4*)(u + gofs);
                float yy[4] = {y4.x, y4.y, y4.z, y4.w};
                float uu[4] = {u4.x, u4.y, u4.z, u4.w};
                float rr[4];
                #pragma unroll
                for (int t = 0; t < 4; t++) {
                    float x  = yy[t] + uu[t] * Dd;
                    float tc = (2.0f * x - 10.0f) * 0.05f;
                    float t0 = 1.0f, t1 = tc;
                    float res = 6.04831644882f + 8.094460228971f * tc;
                    #pragma unroll
                    for (int q = 0; q < 5; q++) {
                        float ti = 2.0f * tc * t1 - t0;
                        res += cc5[q] * ti;
                        t0 = t1; t1 = ti;
                    }
                    rr[t] = res;
                }
                float4 r4 = {rr[0], rr[1], rr[2], rr[3]};
                *(float4*)(g_act + gofs) = r4;
            }
        }
        __syncthreads();
    }
}

// ---------------------------------------------------------------------------
// Kernel C (tensor): GLU GEMM + gate + Wdec-pool via mma.sync bf16 hi/lo.
// CTA = (l-chunk of 64, batch b), grid (16, 32), 256 threads = 8 warps.
// Warp w computes m-tile pair (w, w+8): o rows [16w,16w+16) (a-half) and
// [128+16w, 128+16w+16) (gate-half) -> accA/accB fragments align per thread.
// A frags from pre-split g_W1h/g_W1l (gmem, L1-hot). B tile: g_act slice
// transposed to smem [l][d] bf16 hi/lo (pitch 68 u32 -> conflict-free frags).
// ---------------------------------------------------------------------------
__global__ void __launch_bounds__(256) k_head(const float* __restrict__ b1,
                                              const float* __restrict__ Wdec,
                                              float* __restrict__ out)
{
    __shared__ uint32_t Bh[64 * 68];      // [l][d/2] hi pairs, pitch 68 u32
    __shared__ uint32_t Bl[64 * 68];
    __shared__ float red[256];

    const int tid  = threadIdx.x;
    const int w    = tid >> 5;
    const int lane = tid & 31;
    const int r    = lane >> 2;          // 0..7
    const int kc   = (lane & 3) * 2;     // 0,2,4,6
    const int lc   = blockIdx.x;         // 64-l chunk (0..15)
    const int b    = blockIdx.y;

    // ---- build B tile: g_act[b][d][lc*64 + (0..63)] -> Bh/Bl[l][d] ----
    const float* gsrc = g_act + (size_t)b * D_MODEL * LSEQ + lc * 64;
    for (int idx = tid; idx < 2048; idx += 256) {        // d = idx>>4, l4 = (idx&15)*4
        int dd = idx >> 4, l4 = (idx & 15) * 4;
        float4 v = *(const float4*)(gsrc + (size_t)dd * LSEQ + l4);
        float vv[4] = {v.x, v.y, v.z, v.w};
        #pragma unroll
        for (int t = 0; t < 4; t++) {
            uint16_t h = bfbits(vv[t]);
            uint16_t lo = bfbits(vv[t] - bf2f(h));
            ((uint16_t*)Bh)[(l4 + t) * 136 + dd] = h;
            ((uint16_t*)Bl)[(l4 + t) * 136 + dd] = lo;
        }
    }
    __syncthreads();

    // per-thread biases / weights for the two o-rows this thread owns
    const int oa0 = 16 * w + r, oa1 = oa0 + 8;
    float b1a0 = b1[oa0],        b1a1 = b1[oa1];
    float b1b0 = b1[oa0 + 128],  b1b1 = b1[oa1 + 128];
    float wd0  = Wdec[oa0],      wd1  = Wdec[oa1];

    const uint32_t* W1h32 = (const uint32_t*)g_W1h;
    const uint32_t* W1l32 = (const uint32_t*)g_W1l;

    float partial = 0.0f;

    for (int half = 0; half < 2; half++) {
        float accA[4][4], accB[4][4];
        #pragma unroll
        for (int i = 0; i < 4; i++)
            #pragma unroll
            for (int jq = 0; jq < 4; jq++) { accA[i][jq] = 0.0f; accB[i][jq] = 0.0f; }

        #pragma unroll
        for (int ks = 0; ks < 8; ks++) {
            const int c  = ks * 16 + kc;
            const int cu = c >> 1;                       // u32 index within row
            // A fragments: m-tile w (a-half) rows oa0/oa1; m-tile w+8 -> +128 rows
            const int ra0 = oa0 * 64 + cu, ra1 = oa1 * 64 + cu;
            uint32_t ah0[4], al0[4], ah1[4], al1[4];
            ah0[0] = __ldg(W1h32 + ra0);     ah0[1] = __ldg(W1h32 + ra1);
            ah0[2] = __ldg(W1h32 + ra0 + 4); ah0[3] = __ldg(W1h32 + ra1 + 4);
            al0[0] = __ldg(W1l32 + ra0);     al0[1] = __ldg(W1l32 + ra1);
            al0[2] = __ldg(W1l32 + ra0 + 4); al0[3] = __ldg(W1l32 + ra1 + 4);
            const int rb0 = ra0 + 128 * 64, rb1 = ra1 + 128 * 64;
            ah1[0] = __ldg(W1h32 + rb0);     ah1[1] = __ldg(W1h32 + rb1);
            ah1[2] = __ldg(W1h32 + rb0 + 4); ah1[3] = __ldg(W1h32 + rb1 + 4);
            al1[0] = __ldg(W1l32 + rb0);     al1[1] = __ldg(W1l32 + rb1);
            al1[2] = __ldg(W1l32 + rb0 + 4); al1[3] = __ldg(W1l32 + rb1 + 4);

            #pragma unroll
            for (int nt = 0; nt < 4; nt++) {
                const int lrow = half * 32 + nt * 8 + r;
                uint32_t bh[2] = { Bh[lrow * 68 + cu], Bh[lrow * 68 + cu + 4] };
                uint32_t bl[2] = { Bl[lrow * 68 + cu], Bl[lrow * 68 + cu + 4] };
                mma16816(accA[nt], ah0, bh);
                mma16816(accA[nt], ah0, bl);
                mma16816(accA[nt], al0, bh);
                mma16816(accB[nt], ah1, bh);
                mma16816(accB[nt], ah1, bl);
                mma16816(accB[nt], al1, bh);
            }
        }

        // gate + Wdec-weighted accumulate (uniform over l)
        #pragma unroll
        for (int nt = 0; nt < 4; nt++) {
            #pragma unroll
            for (int cq = 0; cq < 4; cq++) {
                float ba  = (cq < 2) ? b1a0 : b1a1;
                float bb  = (cq < 2) ? b1b0 : b1b1;
                float wdv = (cq < 2) ? wd0  : wd1;
                float a    = accA[nt][cq] + ba;
                float gv   = accB[nt][cq] + bb;
                float gate = fminf(fmaxf(0.25f * gv + 0.5f, 0.0f), 1.0f);
                partial += wdv * (a * gate);
            }
        }
    }

    red[tid] = partial;
    __syncthreads();
    for (int s = 128; s > 0; s >>= 1) {
        if (tid < s) red[tid] += red[tid + s];
        __syncthreads();
    }
    if (tid == 0) atomicAdd(out + b, red[0] * (1.0f / 1024.0f));
}

__global__ void k_init(float* out, const float* __restrict__ bdec)
{
    int i = threadIdx.x;
    if (i < BATCH) out[i] = bdec[0];
}

// ---------------------------------------------------------------------------
extern "C" void kernel_launch(void* const* d_in, const int* in_sizes, int n_in,
                              void* d_out, int out_size)
{
    const float* u          = (const float*)d_in[0];
    const float* log_dt     = (const float*)d_in[1];
    const float* log_A_real = (const float*)d_in[2];
    const float* A_imag     = (const float*)d_in[3];
    const float* B_re       = (const float*)d_in[4];
    const float* B_im       = (const float*)d_in[5];
    const float* C_re       = (const float*)d_in[6];
    const float* C_im       = (const float*)d_in[7];
    const float* Dvec       = (const float*)d_in[8];
    const float* W1         = (const float*)d_in[9];
    const float* b1         = (const float*)d_in[10];
    const float* Wdec       = (const float*)d_in[11];
    const float* bdec       = (const float*)d_in[12];
    float* out = (float*)d_out;

    cudaFuncSetAttribute(k_conv, cudaFuncAttributeMaxDynamicSharedMemorySize, SMEM_CONV);

    k_init<<<1, 32>>>(out, bdec);
    k_prepW<<<128, 256>>>(W1);
    k_genK<<<dim3(D_MODEL, 4), 256>>>(log_dt, log_A_real, A_imag, B_re, B_im, C_re, C_im);
    k_conv<<<D_MODEL, 256, SMEM_CONV>>>(u, Dvec);
    k_head<<<dim3(16, BATCH), 256>>>(b1, Wdec, out);
}

// round 12
// speedup vs baseline: 6.5578x; 2.0489x over previous
#include <cuda_runtime.h>
#include <cuda_bf16.h>
#include <math.h>
#include <stdint.h>

#define D_MODEL 128
#define D_STATE 64
#define LSEQ    1024
#define BATCH   32

// Scratch (static device globals: allocation-free per harness rules)
__device__ float g_K  [D_MODEL * LSEQ];                  // REVERSED kernel Krev[d][s] = K[d][1023-s]
__device__ float g_act[BATCH * D_MODEL * LSEQ];          // post-GELU activations
__device__ uint32_t g_Wfh[16384];                        // W1 hi, mma-fragment order
__device__ uint32_t g_Wfl[16384];                        // W1 lo, mma-fragment order

// ---------------------------------------------------------------------------
// helpers
// ---------------------------------------------------------------------------
__device__ __forceinline__ uint16_t bfbits(float x) {
    __nv_bfloat16 h = __float2bfloat16(x);
    return *(uint16_t*)&h;
}
__device__ __forceinline__ float bf2f(uint16_t b) {
    __nv_bfloat16 h = *(__nv_bfloat16*)&b;
    return __bfloat162float(h);
}
// mma.sync m16n8k16 row.col f32.bf16.bf16.f32 (sm_80+, no 'a' feature needed)
__device__ __forceinline__ void mma16816(float* c, const uint32_t* a, const uint32_t* b) {
    asm volatile(
        "mma.sync.aligned.m16n8k16.row.col.f32.bf16.bf16.f32 "
        "{%0,%1,%2,%3}, {%4,%5,%6,%7}, {%8,%9}, {%0,%1,%2,%3};"
        : "+f"(c[0]), "+f"(c[1]), "+f"(c[2]), "+f"(c[3])
        : "r"(a[0]), "r"(a[1]), "r"(a[2]), "r"(a[3]), "r"(b[0]), "r"(b[1]));
}

// fp32 Cody-Waite mod-2pi of an fp32 value (exact enough: err <= ~7e-7 abs).
// C1=6.28125 has a 7-bit mantissa: n*C1 exact for n<=2^13; ph-n*C1 exact
// (Sterbenz); only the C2 term rounds.
__device__ __forceinline__ float red2pi(float ph) {
    float n = rintf(ph * 0.15915494309189535f);
    float r = fmaf(n, -6.28125f, ph);
    return fmaf(n, -1.9353071795864769e-3f, r);
}

// ---------------------------------------------------------------------------
// Kernel A: K[d,m], stored REVERSED: g_K[d][1023-m] = K[d][m]
// ---------------------------------------------------------------------------
__global__ void k_genK(const float* __restrict__ log_dt,
                       const float* __restrict__ log_A_real,
                       const float* __restrict__ A_imag,
                       const float* __restrict__ B_re, const float* __restrict__ B_im,
                       const float* __restrict__ C_re, const float* __restrict__ C_im)
{
    const int d = blockIdx.x;
    __shared__ float arS[64], aiS[64], grS[64], giS[64];
    const int tid = threadIdx.x;

    if (tid < 64) {
        int n = tid;
        float dtv = expf(log_dt[d]);
        float Ar  = -expf(log_A_real[d * 64 + n]);
        float Ai  = A_imag[d * 64 + n];
        float ar  = Ar * dtv;
        float ai  = Ai * dtv;
        float r0  = red2pi(ai);
        float s, c;
        __sincosf(r0, &s, &c);
        float e   = expf(ar);
        float Abr = e * c, Abi = e * s;
        float nr = Abr - 1.0f, ni = Abi;
        float inv = 1.0f / (Ar * Ar + Ai * Ai);
        float br = (nr * Ar + ni * Ai) * inv;
        float bi = (ni * Ar - nr * Ai) * inv;
        float Br = B_re[d * 64 + n], Bi = B_im[d * 64 + n];
        float tr = br * Br - bi * Bi;
        float ti = br * Bi + bi * Br;
        float Cr = C_re[d * 64 + n], Ci = C_im[d * 64 + n];
        grS[n] = Cr * tr - Ci * ti;
        giS[n] = Cr * ti + Ci * tr;
        arS[n] = ar;
        aiS[n] = ai;
    }
    __syncthreads();

    const int l = blockIdx.y * 256 + tid;
    float lf = (float)l;
    float acc = 0.0f;
    #pragma unroll 4
    for (int n = 0; n < 64; n++) {
        float ph = aiS[n] * lf;                // fp32 phase (matches reference rounding)
        float r  = red2pi(ph);                 // exact-enough mod 2pi of ph
        float s, c;
        __sincosf(r, &s, &c);
        float e = __expf(arS[n] * lf);
        acc += e * (grS[n] * c - giS[n] * s);
    }
    g_K[d * LSEQ + (LSEQ - 1 - l)] = acc;      // reversed store
}

// ---------------------------------------------------------------------------
// W1 -> bf16 hi/lo in mma-fragment order.
// Fragment layout for k_head: thread (h, w, ks, lane) needs 4 u32:
//   r = lane>>2, cu = ks*8 + (lane&3), oa0 = h*128 + 16w + r, oa1 = oa0+8
//   reg0 = W1[oa0][2cu..2cu+1], reg1 = W1[oa1][2cu..], reg2 = W1[oa0][2cu+8..],
//   reg3 = W1[oa1][2cu+8..]
// Stored contiguously at index ((h*8+w)*8+ks)*32+lane) * 4.
// ---------------------------------------------------------------------------
__global__ void k_prepW(const float* __restrict__ W1)
{
    int t = blockIdx.x * 256 + threadIdx.x;    // 0..4095
    int lane = t & 31;
    int ks = (t >> 5) & 7;
    int w  = (t >> 8) & 7;
    int h  = (t >> 11) & 1;
    int r  = lane >> 2;
    int cu = ks * 8 + (lane & 3);
    int oa0 = h * 128 + 16 * w + r, oa1 = oa0 + 8;
    int rowsel[4] = {oa0, oa1, oa0, oa1};
    int dsel[4]   = {2 * cu, 2 * cu, 2 * cu + 8, 2 * cu + 8};
    uint32_t hi[4], lo[4];
    #pragma unroll
    for (int i = 0; i < 4; i++) {
        float v0 = W1[rowsel[i] * 128 + dsel[i]];
        float v1 = W1[rowsel[i] * 128 + dsel[i] + 1];
        uint16_t h0 = bfbits(v0), h1 = bfbits(v1);
        uint16_t l0 = bfbits(v0 - bf2f(h0)), l1 = bfbits(v1 - bf2f(h1));
        hi[i] = (uint32_t)h0 | ((uint32_t)h1 << 16);
        lo[i] = (uint32_t)l0 | ((uint32_t)l1 << 16);
    }
    uint4 hv = {hi[0], hi[1], hi[2], hi[3]};
    uint4 lv = {lo[0], lo[1], lo[2], lo[3]};
    *(uint4*)&g_Wfh[(size_t)t * 4] = hv;
    *(uint4*)&g_Wfl[(size_t)t * 4] = lv;
}

// ---------------------------------------------------------------------------
// Kernel B: per-d Toeplitz conv via mma.sync bf16 hi/lo split (unchanged).
// ---------------------------------------------------------------------------
#define PKB      2064                     // ub row pitch bytes (1032 bf16)
#define OFF_AH   0                        // 1160 u32 = 4640 B
#define OFF_AL   4640
#define OFF_STG  9280                     // 32*136 floats = 17408 B (also K scratch)
#define OFF_UBH  26688                    // 32 * 2064 = 66048 B
#define OFF_UBL  92736
#define SMEM_CONV 158784

__global__ void __launch_bounds__(256, 1) k_conv(const float* __restrict__ u,
                                                 const float* __restrict__ Dvec)
{
    extern __shared__ __align__(16) char smem[];
    uint32_t* AH  = (uint32_t*)(smem + OFF_AH);
    uint32_t* AL  = (uint32_t*)(smem + OFF_AL);
    float*    stg = (float*)(smem + OFF_STG);

    const int d    = blockIdx.x;
    const int tid  = threadIdx.x;
    const int w    = tid >> 5;
    const int lane = tid & 31;

    for (int i = tid; i < 1024; i += 256) stg[i] = g_K[d * LSEQ + i];
    __syncthreads();

    for (int i = tid; i < 1160; i += 256) {
        int il = i - 8;
        float k0 = (il  >= 128 && il  <= 1151) ? stg[il  - 128] : 0.0f;
        float k1 = (il-1 >= 128 && il-1 <= 1151) ? stg[il - 129] : 0.0f;
        uint16_t h0 = bfbits(k0), h1 = bfbits(k1);
        uint16_t l0 = bfbits(k0 - bf2f(h0)), l1 = bfbits(k1 - bf2f(h1));
        AH[i] = (uint32_t)h0 | ((uint32_t)h1 << 16);
        AL[i] = (uint32_t)l0 | ((uint32_t)l1 << 16);
    }

    for (int idx = tid; idx < 8192; idx += 256) {
        int n = idx >> 8, kq = idx & 255;
        float4 v = *(const float4*)(u + ((size_t)(n * D_MODEL + d)) * LSEQ + kq * 4);
        float vv[4] = {v.x, v.y, v.z, v.w};
        uint16_t hb[4], lb[4];
        #pragma unroll
        for (int t = 0; t < 4; t++) {
            hb[t] = bfbits(vv[t]);
            lb[t] = bfbits(vv[t] - bf2f(hb[t]));
        }
        uint2 hv = { (uint32_t)hb[0] | ((uint32_t)hb[1] << 16),
                     (uint32_t)hb[2] | ((uint32_t)hb[3] << 16) };
        uint2 lv = { (uint32_t)lb[0] | ((uint32_t)lb[1] << 16),
                     (uint32_t)lb[2] | ((uint32_t)lb[3] << 16) };
        *(uint2*)(smem + OFF_UBH + n * PKB + kq * 8) = hv;
        *(uint2*)(smem + OFF_UBL + n * PKB + kq * 8) = lv;
    }
    __syncthreads();

    const uint32_t* AHl = AH + 8;
    const uint32_t* ALl = AL + 8;
    const int row  = lane >> 2;
    const int kc   = (lane & 3) * 2;
    const float Dd = Dvec[d];
    const float cc5[5] = {1.371512430522f, -0.740775295685f, 0.134773988002f,
                          0.126019270103f, -0.239569101196f};

    for (int j = 0; j < 8; j++) {
        float acc[4][4];
        #pragma unroll
        for (int a = 0; a < 4; a++)
            #pragma unroll
            for (int b = 0; b < 4; b++) acc[a][b] = 0.0f;

        const int nk = 8 * (j + 1);
        const int Pw = 128 + j * 128 + w * 16 + row - kc;

        for (int kk = 0; kk < nk; kk++) {
            const int k0 = kk * 16;
            const int p  = Pw - k0;
            uint32_t ah[4], al[4];
            ah[0] = AHl[p]; ah[1] = AHl[p + 8]; ah[2] = AHl[p - 8]; ah[3] = ah[0];
            al[0] = ALl[p]; al[1] = ALl[p + 8]; al[2] = ALl[p - 8]; al[3] = al[0];
            const int bofs = (k0 + kc) * 2;
            #pragma unroll
            for (int nt = 0; nt < 4; nt++) {
                const char* pb = smem + (nt * 8 + row) * PKB + bofs;
                uint32_t bh[2] = { *(const uint32_t*)(pb + OFF_UBH),
                                   *(const uint32_t*)(pb + OFF_UBH + 16) };
                uint32_t bl[2] = { *(const uint32_t*)(pb + OFF_UBL),
                                   *(const uint32_t*)(pb + OFF_UBL + 16) };
                mma16816(acc[nt], ah, bh);
                mma16816(acc[nt], ah, bl);
                mma16816(acc[nt], al, bh);
            }
        }

        #pragma unroll
        for (int nt = 0; nt < 4; nt++) {
            int bcol = nt * 8 + kc;
            int lml  = w * 16 + row;
            stg[bcol * 136 + lml]           = acc[nt][0];
            stg[(bcol + 1) * 136 + lml]     = acc[nt][1];
            stg[bcol * 136 + lml + 8]       = acc[nt][2];
            stg[(bcol + 1) * 136 + lml + 8] = acc[nt][3];
        }
        __syncthreads();

        {
            const int bq  = tid >> 3;
            const int l4  = (tid & 7) * 4;
            #pragma unroll
            for (int i = 0; i < 4; i++) {
                const int ll = l4 + i * 32;
                const int l  = j * 128 + ll;
                float4 y4 = *(const float4*)&stg[bq * 136 + ll];
                const size_t gofs = ((size_t)(bq * D_MODEL + d)) * LSEQ + l;
                float4 u4 = *(const float4*)(u + gofs);
                float yy[4] = {y4.x, y4.y, y4.z, y4.w};
                float uu[4] = {u4.x, u4.y, u4.z, u4.w};
                float rr[4];
                #pragma unroll
                for (int t = 0; t < 4; t++) {
                    float x  = yy[t] + uu[t] * Dd;
                    float tc = (2.0f * x - 10.0f) * 0.05f;
                    float t0 = 1.0f, t1 = tc;
                    float res = 6.04831644882f + 8.094460228971f * tc;
                    #pragma unroll
                    for (int q = 0; q < 5; q++) {
                        float ti = 2.0f * tc * t1 - t0;
                        res += cc5[q] * ti;
                        t0 = t1; t1 = ti;
                    }
                    rr[t] = res;
                }
                float4 r4 = {rr[0], rr[1], rr[2], rr[3]};
                *(float4*)(g_act + gofs) = r4;
            }
        }
        __syncthreads();
    }
}

// ---------------------------------------------------------------------------
// Kernel C (tensor): GLU GEMM + gate + Wdec-pool via mma.sync bf16 hi/lo.
// CTA = (l-chunk of 64, batch b), grid (16, 32), 256 threads = 8 warps.
// ks is the OUTER loop: A fragments = 4x LDG.128 from the fragment-packed
// g_Wfh/g_Wfl, reused across both l-halves (acc for both halves in regs).
// ---------------------------------------------------------------------------
__global__ void __launch_bounds__(256) k_head(const float* __restrict__ b1,
                                              const float* __restrict__ Wdec,
                                              float* __restrict__ out)
{
    __shared__ uint32_t Bh[64 * 68];      // [l][d/2] hi pairs, pitch 68 u32
    __shared__ uint32_t Bl[64 * 68];
    __shared__ float red[256];

    const int tid  = threadIdx.x;
    const int w    = tid >> 5;
    const int lane = tid & 31;
    const int r    = lane >> 2;          // 0..7
    const int lc   = blockIdx.x;         // 64-l chunk (0..15)
    const int b    = blockIdx.y;

    // ---- build B tile: g_act[b][d][lc*64 + (0..63)] -> Bh/Bl[l][d] ----
    const float* gsrc = g_act + (size_t)b * D_MODEL * LSEQ + lc * 64;
    for (int idx = tid; idx < 2048; idx += 256) {
        int dd = idx >> 4, l4 = (idx & 15) * 4;
        float4 v = *(const float4*)(gsrc + (size_t)dd * LSEQ + l4);
        float vv[4] = {v.x, v.y, v.z, v.w};
        #pragma unroll
        for (int t = 0; t < 4; t++) {
            uint16_t h = bfbits(vv[t]);
            uint16_t lo = bfbits(vv[t] - bf2f(h));
            ((uint16_t*)Bh)[(l4 + t) * 136 + dd] = h;
            ((uint16_t*)Bl)[(l4 + t) * 136 + dd] = lo;
        }
    }
    __syncthreads();

    const int oa0 = 16 * w + r, oa1 = oa0 + 8;
    float b1a0 = b1[oa0],        b1a1 = b1[oa1];
    float b1b0 = b1[oa0 + 128],  b1b1 = b1[oa1 + 128];
    float wd0  = Wdec[oa0],      wd1  = Wdec[oa1];

    float accA[2][4][4], accB[2][4][4];
    #pragma unroll
    for (int lh = 0; lh < 2; lh++)
        #pragma unroll
        for (int nt = 0; nt < 4; nt++)
            #pragma unroll
            for (int q = 0; q < 4; q++) { accA[lh][nt][q] = 0.0f; accB[lh][nt][q] = 0.0f; }

    #pragma unroll
    for (int ks = 0; ks < 8; ks++) {
        const int fidx0 = (((0 * 8 + w) * 8 + ks) * 32 + lane) * 4;   // a-half
        const int fidx1 = (((1 * 8 + w) * 8 + ks) * 32 + lane) * 4;   // gate-half
        uint4 AH0 = *(const uint4*)&g_Wfh[fidx0];
        uint4 AL0 = *(const uint4*)&g_Wfl[fidx0];
        uint4 AH1 = *(const uint4*)&g_Wfh[fidx1];
        uint4 AL1 = *(const uint4*)&g_Wfl[fidx1];
        uint32_t ah0[4] = {AH0.x, AH0.y, AH0.z, AH0.w};
        uint32_t al0[4] = {AL0.x, AL0.y, AL0.z, AL0.w};
        uint32_t ah1[4] = {AH1.x, AH1.y, AH1.z, AH1.w};
        uint32_t al1[4] = {AL1.x, AL1.y, AL1.z, AL1.w};
        const int cu = ks * 8 + (lane & 3);

        #pragma unroll
        for (int lh = 0; lh < 2; lh++) {
            #pragma unroll
            for (int nt = 0; nt < 4; nt++) {
                const int lrow = lh * 32 + nt * 8 + r;
                uint32_t bh[2] = { Bh[lrow * 68 + cu], Bh[lrow * 68 + cu + 4] };
                uint32_t bl[2] = { Bl[lrow * 68 + cu], Bl[lrow * 68 + cu + 4] };
                mma16816(accA[lh][nt], ah0, bh);
                mma16816(accA[lh][nt], ah0, bl);
                mma16816(accA[lh][nt], al0, bh);
                mma16816(accB[lh][nt], ah1, bh);
                mma16816(accB[lh][nt], ah1, bl);
                mma16816(accB[lh][nt], al1, bh);
            }
        }
    }

    // gate + Wdec-weighted accumulate (uniform over l)
    float partial = 0.0f;
    #pragma unroll
    for (int lh = 0; lh < 2; lh++)
        #pragma unroll
        for (int nt = 0; nt < 4; nt++)
            #pragma unroll
            for (int cq = 0; cq < 4; cq++) {
                float ba  = (cq < 2) ? b1a0 : b1a1;
                float bb  = (cq < 2) ? b1b0 : b1b1;
                float wdv = (cq < 2) ? wd0  : wd1;
                float a    = accA[lh][nt][cq] + ba;
                float gv   = accB[lh][nt][cq] + bb;
                float gate = fminf(fmaxf(0.25f * gv + 0.5f, 0.0f), 1.0f);
                partial += wdv * (a * gate);
            }

    red[tid] = partial;
    __syncthreads();
    for (int s = 128; s > 0; s >>= 1) {
        if (tid < s) red[tid] += red[tid + s];
        __syncthreads();
    }
    if (tid == 0) atomicAdd(out + b, red[0] * (1.0f / 1024.0f));
}

__global__ void k_init(float* out, const float* __restrict__ bdec)
{
    int i = threadIdx.x;
    if (i < BATCH) out[i] = bdec[0];
}

// ---------------------------------------------------------------------------
extern "C" void kernel_launch(void* const* d_in, const int* in_sizes, int n_in,
                              void* d_out, int out_size)
{
    const float* u          = (const float*)d_in[0];
    const float* log_dt     = (const float*)d_in[1];
    const float* log_A_real = (const float*)d_in[2];
    const float* A_imag     = (const float*)d_in[3];
    const float* B_re       = (const float*)d_in[4];
    const float* B_im       = (const float*)d_in[5];
    const float* C_re       = (const float*)d_in[6];
    const float* C_im       = (const float*)d_in[7];
    const float* Dvec       = (const float*)d_in[8];
    const float* W1         = (const float*)d_in[9];
    const float* b1         = (const float*)d_in[10];
    const float* Wdec       = (const float*)d_in[11];
    const float* bdec       = (const float*)d_in[12];
    float* out = (float*)d_out;

    cudaFuncSetAttribute(k_conv, cudaFuncAttributeMaxDynamicSharedMemorySize, SMEM_CONV);

    k_init<<<1, 32>>>(out, bdec);
    k_prepW<<<16, 256>>>(W1);
    k_genK<<<dim3(D_MODEL, 4), 256>>>(log_dt, log_A_real, A_imag, B_re, B_im, C_re, C_im);
    k_conv<<<D_MODEL, 256, SMEM_CONV>>>(u, Dvec);
    k_head<<<dim3(16, BATCH), 256>>>(b1, Wdec, out);
}